// round 7
// baseline (speedup 1.0000x reference)
#include <cuda_runtime.h>
#include <cstdint>

#define Dk 64
#define NTHREADS 256

// smem byte offsets
#define SM_XS 0          // 128 rows x 256B (64 fp32/tf32), swizzled
#define SM_YS 32768
#define SM_XN 65536
#define SM_YN 66048
#define SM_TOTAL 66560

__device__ __forceinline__ uint32_t smem_u32(const void* p) {
    uint32_t a;
    asm("{ .reg .u64 t; cvta.to.shared.u64 t, %1; cvt.u32.u64 %0, t; }" : "=r"(a) : "l"(p));
    return a;
}
__device__ __forceinline__ uint32_t cvt_tf32(float f) {
    uint32_t r;
    asm("cvt.rna.tf32.f32 %0, %1;" : "=r"(r) : "f"(f));
    return r;
}
__device__ __forceinline__ void ldsm_x4(uint32_t addr, uint32_t& r0, uint32_t& r1,
                                        uint32_t& r2, uint32_t& r3) {
    asm volatile("ldmatrix.sync.aligned.m8n8.x4.shared.b16 {%0,%1,%2,%3}, [%4];"
                 : "=r"(r0), "=r"(r1), "=r"(r2), "=r"(r3) : "r"(addr));
}
__device__ __forceinline__ void mma_tf32(float& c0, float& c1, float& c2, float& c3,
                                         uint32_t a0, uint32_t a1, uint32_t a2, uint32_t a3,
                                         uint32_t b0, uint32_t b1) {
    asm volatile(
        "mma.sync.aligned.m16n8k8.row.col.f32.tf32.tf32.f32 "
        "{%0,%1,%2,%3}, {%4,%5,%6,%7}, {%8,%9}, {%0,%1,%2,%3};"
        : "+f"(c0), "+f"(c1), "+f"(c2), "+f"(c3)
        : "r"(a0), "r"(a1), "r"(a2), "r"(a3), "r"(b0), "r"(b1));
}

extern __shared__ char smem[];

// Loads 128 rows (2 threads per row) of fp32[64], scaled, converted to tf32,
// stored swizzled into dst; row norms (of UNSCALED values) into nrm.
__device__ __forceinline__ void load_tile(const float* __restrict__ src_base,
                                          char* dst, float* nrm,
                                          int tid, int n_unused, float scale) {
    const int rr = tid >> 1;
    const int h  = tid & 1;
    const float* src = src_base + (size_t)rr * Dk + h * 32;
    char* row = dst + rr * 256;
    const uint32_t rx = (uint32_t)(rr & 7) << 4;

    float p = 0.0f;
    #pragma unroll
    for (int i4 = 0; i4 < 8; i4++) {
        float4 v = *(const float4*)(src + i4 * 4);
        p = fmaf(v.x, v.x, p); p = fmaf(v.y, v.y, p);
        p = fmaf(v.z, v.z, p); p = fmaf(v.w, v.w, p);
        uint4 w;
        w.x = cvt_tf32(scale * v.x);
        w.y = cvt_tf32(scale * v.y);
        w.z = cvt_tf32(scale * v.z);
        w.w = cvt_tf32(scale * v.w);
        uint32_t g = (uint32_t)(h * 8 + i4) << 4;
        *(uint4*)(row + (g ^ rx)) = w;
    }
    p += __shfl_xor_sync(0xFFFFFFFFu, p, 1);
    if (h == 0) nrm[rr] = p;
}

__global__ __launch_bounds__(NTHREADS, 2)
void PairwiseDistance_tf32_kernel(const float* __restrict__ x,
                                  const float* __restrict__ y,
                                  float* __restrict__ out, int n) {
    const uint32_t sbase = smem_u32(smem);
    const int tid  = threadIdx.x;
    const int wid  = tid >> 5;
    const int lane = tid & 31;

    const int b  = blockIdx.z;
    const int i0 = blockIdx.y * 128;
    const int jbase = blockIdx.x * 256;
    const float* xb = x + (size_t)b * n * Dk;
    const float* yb = y + (size_t)b * n * Dk;
    float* ob = out + (size_t)b * n * n;

    float* xn = (float*)(smem + SM_XN);
    float* yn = (float*)(smem + SM_YN);

    // ---- Prologue: x tile + first y tile ----
    load_tile(xb + (size_t)i0 * Dk, smem + SM_XS, xn, tid, n, -2.0f);
    load_tile(yb + (size_t)jbase * Dk, smem + SM_YS, yn, tid, n, 1.0f);
    __syncthreads();

    // warp tiling: 2x4 warps, warp tile 64(m) x 32(n)
    const int wy = wid >> 2, wx = wid & 3;
    const int m_warp = wy * 64, n_warp = wx * 32;
    const uint32_t l7 = (uint32_t)(lane & 7);

    // ldmatrix bases
    const uint32_t aRow = (uint32_t)(m_warp + (lane & 15));
    const uint32_t aH   = (lane & 16) ? 1u : 0u;
    const uint32_t bRow = (uint32_t)(n_warp + (lane & 7) + ((lane & 16) ? 8 : 0));
    const uint32_t bH   = (lane & 8) ? 1u : 0u;
    const uint32_t Abase = sbase + SM_XS + aRow * 256u;
    const uint32_t Bbase = sbase + SM_YS + bRow * 256u;

    const int mrow = lane >> 2;
    const int ncol = 2 * (lane & 3);

    #pragma unroll 1
    for (int jt = 0; jt < 2; jt++) {
        const int j0 = jbase + jt * 128;

        float c[4][4][4];
        #pragma unroll
        for (int mt = 0; mt < 4; mt++)
            #pragma unroll
            for (int nt = 0; nt < 4; nt++) {
                c[mt][nt][0] = 0.f; c[mt][nt][1] = 0.f;
                c[mt][nt][2] = 0.f; c[mt][nt][3] = 0.f;
            }

        #pragma unroll
        for (int kk = 0; kk < 8; kk++) {
            const uint32_t aoff = (((uint32_t)(kk * 2) + aH) ^ l7) << 4;
            const uint32_t boff = (((uint32_t)(kk * 2) + bH) ^ l7) << 4;

            uint32_t a[4][4];
            #pragma unroll
            for (int mt = 0; mt < 4; mt++)
                ldsm_x4(Abase + (uint32_t)mt * 4096u + aoff,
                        a[mt][0], a[mt][1], a[mt][2], a[mt][3]);

            uint32_t bf[4][2];
            #pragma unroll
            for (int ntp = 0; ntp < 2; ntp++) {
                uint32_t r0, r1, r2, r3;
                ldsm_x4(Bbase + (uint32_t)ntp * 4096u + boff, r0, r1, r2, r3);
                bf[ntp * 2 + 0][0] = r0; bf[ntp * 2 + 0][1] = r1;
                bf[ntp * 2 + 1][0] = r2; bf[ntp * 2 + 1][1] = r3;
            }

            #pragma unroll
            for (int mt = 0; mt < 4; mt++)
                #pragma unroll
                for (int nt = 0; nt < 4; nt++)
                    mma_tf32(c[mt][nt][0], c[mt][nt][1], c[mt][nt][2], c[mt][nt][3],
                             a[mt][0], a[mt][1], a[mt][2], a[mt][3],
                             bf[nt][0], bf[nt][1]);
        }

        // snapshot norms needed by this epilogue before ys/yn are overwritten
        float2 ynr[4];
        #pragma unroll
        for (int nt = 0; nt < 4; nt++)
            ynr[nt] = *(const float2*)(yn + n_warp + nt * 8 + ncol);
        float xnr[8];
        #pragma unroll
        for (int mt = 0; mt < 4; mt++) {
            xnr[2 * mt + 0] = xn[m_warp + mt * 16 + mrow];
            xnr[2 * mt + 1] = xn[m_warp + mt * 16 + mrow + 8];
        }

        __syncthreads();
        if (jt == 0) {
            // start loading next y tile; its LDGs overlap our epilogue STGs
            load_tile(yb + (size_t)(jbase + 128) * Dk, smem + SM_YS, yn, tid, n, 1.0f);
        }

        // ---- Epilogue: out = dot + xn[i] + yn[j] ----
        #pragma unroll
        for (int mt = 0; mt < 4; mt++) {
            const int m_lo = m_warp + mt * 16 + mrow;
            const float xn_lo = xnr[2 * mt + 0];
            const float xn_hi = xnr[2 * mt + 1];
            float* row_lo = ob + (size_t)(i0 + m_lo) * n + j0 + n_warp;
            float* row_hi = row_lo + (size_t)8 * n;
            #pragma unroll
            for (int nt = 0; nt < 4; nt++) {
                float2 o0, o1;
                o0.x = c[mt][nt][0] + xn_lo + ynr[nt].x;
                o0.y = c[mt][nt][1] + xn_lo + ynr[nt].y;
                o1.x = c[mt][nt][2] + xn_hi + ynr[nt].x;
                o1.y = c[mt][nt][3] + xn_hi + ynr[nt].y;
                *(float2*)(row_lo + nt * 8 + ncol) = o0;
                *(float2*)(row_hi + nt * 8 + ncol) = o1;
            }
        }

        if (jt == 0) __syncthreads();
    }
}

extern "C" void kernel_launch(void* const* d_in, const int* in_sizes, int n_in,
                              void* d_out, int out_size) {
    const float* x = (const float*)d_in[0];
    const float* y = (const float*)d_in[1];
    float* out = (float*)d_out;

    const int B = 2;
    int n = in_sizes[0] / (B * Dk);       // 2048
    if (n <= 0) n = 2048;

    cudaFuncSetAttribute(PairwiseDistance_tf32_kernel,
                         cudaFuncAttributeMaxDynamicSharedMemorySize, SM_TOTAL);

    dim3 grid(n / 256, n / 128, B);
    PairwiseDistance_tf32_kernel<<<grid, NTHREADS, SM_TOTAL>>>(x, y, out, n);
}

// round 9
// speedup vs baseline: 1.2178x; 1.2178x over previous
#include <cuda_runtime.h>
#include <cstdint>

#define Dk 64
#define NTHREADS 256

// smem byte offsets
#define SM_XS 0          // 128 rows x 256B (tf32), swizzled
#define SM_YS 32768      // 64 rows x 256B
#define SM_XN 49152      // 128 floats
#define SM_YN 49664      // 64 floats
#define SM_TOTAL 49920

__device__ __forceinline__ uint32_t smem_u32(const void* p) {
    uint32_t a;
    asm("{ .reg .u64 t; cvta.to.shared.u64 t, %1; cvt.u32.u64 %0, t; }" : "=r"(a) : "l"(p));
    return a;
}
__device__ __forceinline__ uint32_t cvt_tf32(float f) {
    uint32_t r;
    asm("cvt.rna.tf32.f32 %0, %1;" : "=r"(r) : "f"(f));
    return r;
}
__device__ __forceinline__ void ldsm_x4(uint32_t addr, uint32_t& r0, uint32_t& r1,
                                        uint32_t& r2, uint32_t& r3) {
    asm volatile("ldmatrix.sync.aligned.m8n8.x4.shared.b16 {%0,%1,%2,%3}, [%4];"
                 : "=r"(r0), "=r"(r1), "=r"(r2), "=r"(r3) : "r"(addr));
}
__device__ __forceinline__ void mma_tf32(float& c0, float& c1, float& c2, float& c3,
                                         uint32_t a0, uint32_t a1, uint32_t a2, uint32_t a3,
                                         uint32_t b0, uint32_t b1) {
    asm volatile(
        "mma.sync.aligned.m16n8k8.row.col.f32.tf32.tf32.f32 "
        "{%0,%1,%2,%3}, {%4,%5,%6,%7}, {%8,%9}, {%0,%1,%2,%3};"
        : "+f"(c0), "+f"(c1), "+f"(c2), "+f"(c3)
        : "r"(a0), "r"(a1), "r"(a2), "r"(a3), "r"(b0), "r"(b1));
}

extern __shared__ char smem[];

__global__ __launch_bounds__(NTHREADS, 3)
void PairwiseDistance_tf32_kernel(const float* __restrict__ x,
                                  const float* __restrict__ y,
                                  float* __restrict__ out, int n) {
    const uint32_t sbase = smem_u32(smem);
    const int tid  = threadIdx.x;
    const int wid  = tid >> 5;
    const int lane = tid & 31;

    const int b  = blockIdx.z;
    const int i0 = blockIdx.y * 128;
    const int j0 = blockIdx.x * 64;
    const float* xb = x + (size_t)b * n * Dk;
    const float* yb = y + (size_t)b * n * Dk;
    float* ob = out + (size_t)b * n * n;

    float* xn = (float*)(smem + SM_XN);
    float* yn = (float*)(smem + SM_YN);

    // ---- Prologue ----
    // x tile: 128 rows, 2 threads/row, scaled by -2, tf32, swizzled
    {
        const int rr = tid >> 1;
        const int h  = tid & 1;
        const float* src = xb + (size_t)(i0 + rr) * Dk + h * 32;
        char* row = smem + SM_XS + rr * 256;
        const uint32_t rx = (uint32_t)(rr & 7) << 4;
        float p = 0.0f;
        #pragma unroll
        for (int i4 = 0; i4 < 8; i4++) {
            float4 v = *(const float4*)(src + i4 * 4);
            p = fmaf(v.x, v.x, p); p = fmaf(v.y, v.y, p);
            p = fmaf(v.z, v.z, p); p = fmaf(v.w, v.w, p);
            uint4 w;
            w.x = cvt_tf32(-2.0f * v.x);
            w.y = cvt_tf32(-2.0f * v.y);
            w.z = cvt_tf32(-2.0f * v.z);
            w.w = cvt_tf32(-2.0f * v.w);
            uint32_t g = (uint32_t)(h * 8 + i4) << 4;
            *(uint4*)(row + (g ^ rx)) = w;
        }
        p += __shfl_xor_sync(0xFFFFFFFFu, p, 1);
        if (h == 0) xn[rr] = p;
    }
    // y tile: 64 rows, 4 threads/row, unscaled
    {
        const int rr = tid >> 2;
        const int q  = tid & 3;
        const float* src = yb + (size_t)(j0 + rr) * Dk + q * 16;
        char* row = smem + SM_YS + rr * 256;
        const uint32_t rx = (uint32_t)(rr & 7) << 4;
        float p = 0.0f;
        #pragma unroll
        for (int i4 = 0; i4 < 4; i4++) {
            float4 v = *(const float4*)(src + i4 * 4);
            p = fmaf(v.x, v.x, p); p = fmaf(v.y, v.y, p);
            p = fmaf(v.z, v.z, p); p = fmaf(v.w, v.w, p);
            uint4 w;
            w.x = cvt_tf32(v.x);
            w.y = cvt_tf32(v.y);
            w.z = cvt_tf32(v.z);
            w.w = cvt_tf32(v.w);
            uint32_t g = (uint32_t)(q * 4 + i4) << 4;
            *(uint4*)(row + (g ^ rx)) = w;
        }
        p += __shfl_xor_sync(0xFFFFFFFFu, p, 1);
        p += __shfl_xor_sync(0xFFFFFFFFu, p, 2);
        if (q == 0) yn[rr] = p;
    }
    __syncthreads();

    // ---- Warp tiling: 4x2 warps, warp tile 32(m) x 32(n) ----
    const int m_warp = (wid & 3) * 32;
    const int n_warp = (wid >> 2) * 32;
    const uint32_t l7 = (uint32_t)(lane & 7);

    const uint32_t aRow = (uint32_t)(m_warp + (lane & 15));
    const uint32_t aH   = (lane & 16) ? 1u : 0u;
    const uint32_t bRow = (uint32_t)(n_warp + (lane & 7) + ((lane & 16) ? 8 : 0));
    const uint32_t bH   = (lane & 8) ? 1u : 0u;
    const uint32_t Abase = sbase + SM_XS + aRow * 256u;
    const uint32_t Bbase = sbase + SM_YS + bRow * 256u;

    float c[2][4][4];
    #pragma unroll
    for (int mt = 0; mt < 2; mt++)
        #pragma unroll
        for (int nt = 0; nt < 4; nt++) {
            c[mt][nt][0] = 0.f; c[mt][nt][1] = 0.f;
            c[mt][nt][2] = 0.f; c[mt][nt][3] = 0.f;
        }

    #pragma unroll
    for (int kk = 0; kk < 8; kk++) {
        const uint32_t aoff = (((uint32_t)(kk * 2) + aH) ^ l7) << 4;
        const uint32_t boff = (((uint32_t)(kk * 2) + bH) ^ l7) << 4;

        uint32_t a[2][4];
        #pragma unroll
        for (int mt = 0; mt < 2; mt++)
            ldsm_x4(Abase + (uint32_t)mt * 4096u + aoff,
                    a[mt][0], a[mt][1], a[mt][2], a[mt][3]);

        uint32_t bf[4][2];
        #pragma unroll
        for (int ntp = 0; ntp < 2; ntp++) {
            uint32_t r0, r1, r2, r3;
            ldsm_x4(Bbase + (uint32_t)ntp * 4096u + boff, r0, r1, r2, r3);
            bf[ntp * 2 + 0][0] = r0; bf[ntp * 2 + 0][1] = r1;
            bf[ntp * 2 + 1][0] = r2; bf[ntp * 2 + 1][1] = r3;
        }

        #pragma unroll
        for (int mt = 0; mt < 2; mt++)
            #pragma unroll
            for (int nt = 0; nt < 4; nt++)
                mma_tf32(c[mt][nt][0], c[mt][nt][1], c[mt][nt][2], c[mt][nt][3],
                         a[mt][0], a[mt][1], a[mt][2], a[mt][3],
                         bf[nt][0], bf[nt][1]);
    }

    // ---- Epilogue: out = dot + xn[i] + yn[j] ----
    const int mrow = lane >> 2;
    const int ncol = 2 * (lane & 3);

    float2 ynr[4];
    #pragma unroll
    for (int nt = 0; nt < 4; nt++)
        ynr[nt] = *(const float2*)(yn + n_warp + nt * 8 + ncol);

    #pragma unroll
    for (int mt = 0; mt < 2; mt++) {
        const int m_lo = m_warp + mt * 16 + mrow;
        const float xn_lo = xn[m_lo];
        const float xn_hi = xn[m_lo + 8];
        float* row_lo = ob + (size_t)(i0 + m_lo) * n + j0 + n_warp;
        float* row_hi = row_lo + (size_t)8 * n;
        #pragma unroll
        for (int nt = 0; nt < 4; nt++) {
            float2 o0, o1;
            o0.x = c[mt][nt][0] + xn_lo + ynr[nt].x;
            o0.y = c[mt][nt][1] + xn_lo + ynr[nt].y;
            o1.x = c[mt][nt][2] + xn_hi + ynr[nt].x;
            o1.y = c[mt][nt][3] + xn_hi + ynr[nt].y;
            *(float2*)(row_lo + nt * 8 + ncol) = o0;
            *(float2*)(row_hi + nt * 8 + ncol) = o1;
        }
    }
}

extern "C" void kernel_launch(void* const* d_in, const int* in_sizes, int n_in,
                              void* d_out, int out_size) {
    const float* x = (const float*)d_in[0];
    const float* y = (const float*)d_in[1];
    float* out = (float*)d_out;

    const int B = 2;
    int n = in_sizes[0] / (B * Dk);       // 2048
    if (n <= 0) n = 2048;

    cudaFuncSetAttribute(PairwiseDistance_tf32_kernel,
                         cudaFuncAttributeMaxDynamicSharedMemorySize, SM_TOTAL);

    dim3 grid(n / 64, n / 128, B);
    PairwiseDistance_tf32_kernel<<<grid, NTHREADS, SM_TOTAL>>>(x, y, out, n);
}

// round 10
// speedup vs baseline: 1.2221x; 1.0035x over previous
#include <cuda_runtime.h>
#include <cstdint>

#define Dk 64
#define NTHREADS 256

// smem byte offsets
#define SM_XS 0          // 128 rows x 256B (tf32), swizzled
#define SM_YS 32768      // 64 rows x 256B
#define SM_XN 49152      // 128 floats
#define SM_YN 49664      // 64 floats
#define SM_TOTAL 49920

__device__ __forceinline__ uint32_t smem_u32(const void* p) {
    uint32_t a;
    asm("{ .reg .u64 t; cvta.to.shared.u64 t, %1; cvt.u32.u64 %0, t; }" : "=r"(a) : "l"(p));
    return a;
}
__device__ __forceinline__ uint32_t cvt_tf32(float f) {
    uint32_t r;
    asm("cvt.rna.tf32.f32 %0, %1;" : "=r"(r) : "f"(f));
    return r;
}
__device__ __forceinline__ void ldsm_x4(uint32_t addr, uint32_t& r0, uint32_t& r1,
                                        uint32_t& r2, uint32_t& r3) {
    asm volatile("ldmatrix.sync.aligned.m8n8.x4.shared.b16 {%0,%1,%2,%3}, [%4];"
                 : "=r"(r0), "=r"(r1), "=r"(r2), "=r"(r3) : "r"(addr));
}
__device__ __forceinline__ void mma_tf32(float& c0, float& c1, float& c2, float& c3,
                                         uint32_t a0, uint32_t a1, uint32_t a2, uint32_t a3,
                                         uint32_t b0, uint32_t b1) {
    asm volatile(
        "mma.sync.aligned.m16n8k8.row.col.f32.tf32.tf32.f32 "
        "{%0,%1,%2,%3}, {%4,%5,%6,%7}, {%8,%9}, {%0,%1,%2,%3};"
        : "+f"(c0), "+f"(c1), "+f"(c2), "+f"(c3)
        : "r"(a0), "r"(a1), "r"(a2), "r"(a3), "r"(b0), "r"(b1));
}

extern __shared__ char smem[];

__global__ __launch_bounds__(NTHREADS, 4)
void PairwiseDistance_tf32_kernel(const float* __restrict__ x,
                                  const float* __restrict__ y,
                                  float* __restrict__ out, int n) {
    const uint32_t sbase = smem_u32(smem);
    const int tid  = threadIdx.x;
    const int wid  = tid >> 5;
    const int lane = tid & 31;

    const int b  = blockIdx.z;
    const int i0 = blockIdx.y * 128;
    const int j0 = blockIdx.x * 64;
    const float* xb = x + (size_t)b * n * Dk;
    const float* yb = y + (size_t)b * n * Dk;
    float* ob = out + (size_t)b * n * n;

    float* xn = (float*)(smem + SM_XN);
    float* yn = (float*)(smem + SM_YN);

    // ---- Prologue ----
    // x tile: 128 rows, 2 threads/row, scaled by -2, tf32, swizzled
    {
        const int rr = tid >> 1;
        const int h  = tid & 1;
        const float* src = xb + (size_t)(i0 + rr) * Dk + h * 32;
        char* row = smem + SM_XS + rr * 256;
        const uint32_t rx = (uint32_t)(rr & 7) << 4;
        float p = 0.0f;
        #pragma unroll
        for (int i4 = 0; i4 < 8; i4++) {
            float4 v = *(const float4*)(src + i4 * 4);
            p = fmaf(v.x, v.x, p); p = fmaf(v.y, v.y, p);
            p = fmaf(v.z, v.z, p); p = fmaf(v.w, v.w, p);
            uint4 w;
            w.x = cvt_tf32(-2.0f * v.x);
            w.y = cvt_tf32(-2.0f * v.y);
            w.z = cvt_tf32(-2.0f * v.z);
            w.w = cvt_tf32(-2.0f * v.w);
            uint32_t g = (uint32_t)(h * 8 + i4) << 4;
            *(uint4*)(row + (g ^ rx)) = w;
        }
        p += __shfl_xor_sync(0xFFFFFFFFu, p, 1);
        if (h == 0) xn[rr] = p;
    }
    // y tile: 64 rows, 4 threads/row, unscaled
    {
        const int rr = tid >> 2;
        const int q  = tid & 3;
        const float* src = yb + (size_t)(j0 + rr) * Dk + q * 16;
        char* row = smem + SM_YS + rr * 256;
        const uint32_t rx = (uint32_t)(rr & 7) << 4;
        float p = 0.0f;
        #pragma unroll
        for (int i4 = 0; i4 < 4; i4++) {
            float4 v = *(const float4*)(src + i4 * 4);
            p = fmaf(v.x, v.x, p); p = fmaf(v.y, v.y, p);
            p = fmaf(v.z, v.z, p); p = fmaf(v.w, v.w, p);
            uint4 w;
            w.x = cvt_tf32(v.x);
            w.y = cvt_tf32(v.y);
            w.z = cvt_tf32(v.z);
            w.w = cvt_tf32(v.w);
            uint32_t g = (uint32_t)(q * 4 + i4) << 4;
            *(uint4*)(row + (g ^ rx)) = w;
        }
        p += __shfl_xor_sync(0xFFFFFFFFu, p, 1);
        p += __shfl_xor_sync(0xFFFFFFFFu, p, 2);
        if (q == 0) yn[rr] = p;
    }
    __syncthreads();

    // ---- Warp tiling: 4x2 warps, warp tile 32(m) x 32(n) ----
    const int m_warp = (wid & 3) * 32;
    const int n_warp = (wid >> 2) * 32;
    const uint32_t l7 = (uint32_t)(lane & 7);

    const uint32_t aRow = (uint32_t)(m_warp + (lane & 15));
    const uint32_t aH   = (lane & 16) ? 1u : 0u;
    const uint32_t bRow = (uint32_t)(n_warp + (lane & 7) + ((lane & 16) ? 8 : 0));
    const uint32_t bH   = (lane & 8) ? 1u : 0u;
    const uint32_t Abase = sbase + SM_XS + aRow * 256u;
    const uint32_t Bbase = sbase + SM_YS + bRow * 256u;

    float c[2][4][4];
    #pragma unroll
    for (int mt = 0; mt < 2; mt++)
        #pragma unroll
        for (int nt = 0; nt < 4; nt++) {
            c[mt][nt][0] = 0.f; c[mt][nt][1] = 0.f;
            c[mt][nt][2] = 0.f; c[mt][nt][3] = 0.f;
        }

    #pragma unroll
    for (int kk = 0; kk < 8; kk++) {
        const uint32_t aoff = (((uint32_t)(kk * 2) + aH) ^ l7) << 4;
        const uint32_t boff = (((uint32_t)(kk * 2) + bH) ^ l7) << 4;

        uint32_t a[2][4];
        #pragma unroll
        for (int mt = 0; mt < 2; mt++)
            ldsm_x4(Abase + (uint32_t)mt * 4096u + aoff,
                    a[mt][0], a[mt][1], a[mt][2], a[mt][3]);

        uint32_t bf[4][2];
        #pragma unroll
        for (int ntp = 0; ntp < 2; ntp++) {
            uint32_t r0, r1, r2, r3;
            ldsm_x4(Bbase + (uint32_t)ntp * 4096u + boff, r0, r1, r2, r3);
            bf[ntp * 2 + 0][0] = r0; bf[ntp * 2 + 0][1] = r1;
            bf[ntp * 2 + 1][0] = r2; bf[ntp * 2 + 1][1] = r3;
        }

        #pragma unroll
        for (int mt = 0; mt < 2; mt++)
            #pragma unroll
            for (int nt = 0; nt < 4; nt++)
                mma_tf32(c[mt][nt][0], c[mt][nt][1], c[mt][nt][2], c[mt][nt][3],
                         a[mt][0], a[mt][1], a[mt][2], a[mt][3],
                         bf[nt][0], bf[nt][1]);
    }

    // ---- Epilogue: out = dot + xn[i] + yn[j] ----
    const int mrow = lane >> 2;
    const int ncol = 2 * (lane & 3);

    float2 ynr[4];
    #pragma unroll
    for (int nt = 0; nt < 4; nt++)
        ynr[nt] = *(const float2*)(yn + n_warp + nt * 8 + ncol);

    #pragma unroll
    for (int mt = 0; mt < 2; mt++) {
        const int m_lo = m_warp + mt * 16 + mrow;
        const float xn_lo = xn[m_lo];
        const float xn_hi = xn[m_lo + 8];
        float* row_lo = ob + (size_t)(i0 + m_lo) * n + j0 + n_warp;
        float* row_hi = row_lo + (size_t)8 * n;
        #pragma unroll
        for (int nt = 0; nt < 4; nt++) {
            float2 o0, o1;
            o0.x = c[mt][nt][0] + xn_lo + ynr[nt].x;
            o0.y = c[mt][nt][1] + xn_lo + ynr[nt].y;
            o1.x = c[mt][nt][2] + xn_hi + ynr[nt].x;
            o1.y = c[mt][nt][3] + xn_hi + ynr[nt].y;
            *(float2*)(row_lo + nt * 8 + ncol) = o0;
            *(float2*)(row_hi + nt * 8 + ncol) = o1;
        }
    }
}

extern "C" void kernel_launch(void* const* d_in, const int* in_sizes, int n_in,
                              void* d_out, int out_size) {
    const float* x = (const float*)d_in[0];
    const float* y = (const float*)d_in[1];
    float* out = (float*)d_out;

    const int B = 2;
    int n = in_sizes[0] / (B * Dk);       // 2048
    if (n <= 0) n = 2048;

    cudaFuncSetAttribute(PairwiseDistance_tf32_kernel,
                         cudaFuncAttributeMaxDynamicSharedMemorySize, SM_TOTAL);

    dim3 grid(n / 64, n / 128, B);
    PairwiseDistance_tf32_kernel<<<grid, NTHREADS, SM_TOTAL>>>(x, y, out, n);
}

// round 13
// speedup vs baseline: 1.9224x; 1.5730x over previous
#include <cuda_runtime.h>
#include <cstdint>

#define Dk 64
#define NTHREADS 256

// main-kernel smem byte offsets
#define SM_XS 0          // 128 rows x 256B, swizzled (also reused as out-stage)
#define SM_YS 32768      // 64 rows x 256B
#define SM_XN 49152      // 128 floats
#define SM_YN 49664      // 64 floats
#define SM_TOTAL 49920

// scratch images: pre-swizzled tf32 rows (256B per row), B=2, n=2048
__device__ __align__(16) unsigned char g_xs[2 * 2048 * 256];
__device__ __align__(16) unsigned char g_ys[2 * 2048 * 256];
__device__ __align__(16) float g_xn[2 * 2048];
__device__ __align__(16) float g_yn[2 * 2048];

__device__ __forceinline__ uint32_t smem_u32(const void* p) {
    uint32_t a;
    asm("{ .reg .u64 t; cvta.to.shared.u64 t, %1; cvt.u32.u64 %0, t; }" : "=r"(a) : "l"(p));
    return a;
}
__device__ __forceinline__ uint32_t cvt_tf32(float f) {
    uint32_t r;
    asm("cvt.rna.tf32.f32 %0, %1;" : "=r"(r) : "f"(f));
    return r;
}
__device__ __forceinline__ void cp_async16(uint32_t dst, const void* src) {
    asm volatile("cp.async.cg.shared.global [%0], [%1], 16;"
                 :: "r"(dst), "l"(src) : "memory");
}
__device__ __forceinline__ void ldsm_x4(uint32_t addr, uint32_t& r0, uint32_t& r1,
                                        uint32_t& r2, uint32_t& r3) {
    asm volatile("ldmatrix.sync.aligned.m8n8.x4.shared.b16 {%0,%1,%2,%3}, [%4];"
                 : "=r"(r0), "=r"(r1), "=r"(r2), "=r"(r3) : "r"(addr));
}
__device__ __forceinline__ void mma_tf32(float& c0, float& c1, float& c2, float& c3,
                                         uint32_t a0, uint32_t a1, uint32_t a2, uint32_t a3,
                                         uint32_t b0, uint32_t b1) {
    asm volatile(
        "mma.sync.aligned.m16n8k8.row.col.f32.tf32.tf32.f32 "
        "{%0,%1,%2,%3}, {%4,%5,%6,%7}, {%8,%9}, {%0,%1,%2,%3};"
        : "+f"(c0), "+f"(c1), "+f"(c2), "+f"(c3)
        : "r"(a0), "r"(a1), "r"(a2), "r"(a3), "r"(b0), "r"(b1));
}

// ---- prep: fp32 -> tf32 (rna), -2 folded into x, swizzled row images + norms ----
// one thread per quarter-row (16 elems); rows: x then y, each B*n rows.
__global__ __launch_bounds__(256)
void prep_kernel(const float* __restrict__ x, const float* __restrict__ y, int n) {
    const int gid = blockIdx.x * 256 + threadIdx.x;
    const int row_id = gid >> 2;
    const int q = gid & 3;
    const int Bn = 2 * n;
    if (row_id >= 2 * Bn) return;
    const bool isx = (row_id < Bn);
    const int local = isx ? row_id : row_id - Bn;
    const float scale = isx ? -2.0f : 1.0f;
    const float* src = (isx ? x : y) + (size_t)local * Dk + q * 16;
    unsigned char* img = (isx ? g_xs : g_ys) + (size_t)local * 256;
    const uint32_t rx = (uint32_t)(local & 7) << 4;

    float p = 0.0f;
    #pragma unroll
    for (int i4 = 0; i4 < 4; i4++) {
        float4 v = *(const float4*)(src + i4 * 4);
        p = fmaf(v.x, v.x, p); p = fmaf(v.y, v.y, p);
        p = fmaf(v.z, v.z, p); p = fmaf(v.w, v.w, p);
        uint4 w;
        w.x = cvt_tf32(scale * v.x);
        w.y = cvt_tf32(scale * v.y);
        w.z = cvt_tf32(scale * v.z);
        w.w = cvt_tf32(scale * v.w);
        uint32_t g = (uint32_t)(q * 4 + i4) << 4;
        *(uint4*)(img + (g ^ rx)) = w;
    }
    p += __shfl_xor_sync(0xFFFFFFFFu, p, 1);
    p += __shfl_xor_sync(0xFFFFFFFFu, p, 2);
    if (q == 0) (isx ? g_xn : g_yn)[local] = p;
}

extern __shared__ char smem[];

__global__ __launch_bounds__(NTHREADS, 4)
void PairwiseDistance_tf32_kernel(float* __restrict__ out, int n) {
    const uint32_t sbase = smem_u32(smem);
    const int tid  = threadIdx.x;
    const int wid  = tid >> 5;
    const int lane = tid & 31;

    const int b  = blockIdx.z;
    const int i0 = blockIdx.y * 128;
    const int j0 = blockIdx.x * 64;
    float* ob = out + (size_t)b * n * n;

    // ---- Prologue: cp.async from pre-swizzled images ----
    {
        const unsigned char* xsrc = g_xs + (size_t)(b * n + i0) * 256;
        const unsigned char* ysrc = g_ys + (size_t)(b * n + j0) * 256;
        #pragma unroll
        for (int k2 = 0; k2 < 8; k2++) {
            uint32_t c = (uint32_t)(tid + k2 * 256) * 16u;
            cp_async16(sbase + SM_XS + c, xsrc + c);
        }
        #pragma unroll
        for (int k2 = 0; k2 < 4; k2++) {
            uint32_t c = (uint32_t)(tid + k2 * 256) * 16u;
            cp_async16(sbase + SM_YS + c, ysrc + c);
        }
        if (tid < 32) {
            cp_async16(sbase + SM_XN + tid * 16,
                       (const unsigned char*)(g_xn + b * n + i0) + tid * 16);
        } else if (tid < 48) {
            cp_async16(sbase + SM_YN + (tid - 32) * 16,
                       (const unsigned char*)(g_yn + b * n + j0) + (tid - 32) * 16);
        }
        asm volatile("cp.async.commit_group;" ::: "memory");
        asm volatile("cp.async.wait_group 0;" ::: "memory");
    }
    __syncthreads();

    float* xn = (float*)(smem + SM_XN);
    float* yn = (float*)(smem + SM_YN);

    // ---- Warp tiling: 4x2 warps, warp tile 32(m) x 32(n) ----
    const int m_warp = (wid & 3) * 32;
    const int n_warp = (wid >> 2) * 32;
    const uint32_t l7 = (uint32_t)(lane & 7);

    const uint32_t aRow = (uint32_t)(m_warp + (lane & 15));
    const uint32_t aH   = (lane & 16) ? 1u : 0u;
    const uint32_t bRow = (uint32_t)(n_warp + (lane & 7) + ((lane & 16) ? 8 : 0));
    const uint32_t bH   = (lane & 8) ? 1u : 0u;
    const uint32_t Abase = sbase + SM_XS + aRow * 256u;
    const uint32_t Bbase = sbase + SM_YS + bRow * 256u;

    float c[2][4][4];
    #pragma unroll
    for (int mt = 0; mt < 2; mt++)
        #pragma unroll
        for (int nt = 0; nt < 4; nt++) {
            c[mt][nt][0] = 0.f; c[mt][nt][1] = 0.f;
            c[mt][nt][2] = 0.f; c[mt][nt][3] = 0.f;
        }

    #pragma unroll
    for (int kk = 0; kk < 8; kk++) {
        const uint32_t aoff = (((uint32_t)(kk * 2) + aH) ^ l7) << 4;
        const uint32_t boff = (((uint32_t)(kk * 2) + bH) ^ l7) << 4;

        uint32_t a[2][4];
        #pragma unroll
        for (int mt = 0; mt < 2; mt++)
            ldsm_x4(Abase + (uint32_t)mt * 4096u + aoff,
                    a[mt][0], a[mt][1], a[mt][2], a[mt][3]);

        uint32_t bf[4][2];
        #pragma unroll
        for (int ntp = 0; ntp < 2; ntp++) {
            uint32_t r0, r1, r2, r3;
            ldsm_x4(Bbase + (uint32_t)ntp * 4096u + boff, r0, r1, r2, r3);
            bf[ntp * 2 + 0][0] = r0; bf[ntp * 2 + 0][1] = r1;
            bf[ntp * 2 + 1][0] = r2; bf[ntp * 2 + 1][1] = r3;
        }

        #pragma unroll
        for (int mt = 0; mt < 2; mt++)
            #pragma unroll
            for (int nt = 0; nt < 4; nt++)
                mma_tf32(c[mt][nt][0], c[mt][nt][1], c[mt][nt][2], c[mt][nt][3],
                         a[mt][0], a[mt][1], a[mt][2], a[mt][3],
                         bf[nt][0], bf[nt][1]);
    }

    // ---- Epilogue: add norms, stage into xs (pair-swizzled), coalesced STG.128 ----
    const int mrow = lane >> 2;
    const int ncol = 2 * (lane & 3);

    float2 ynr[4];
    #pragma unroll
    for (int nt = 0; nt < 4; nt++)
        ynr[nt] = *(const float2*)(yn + n_warp + nt * 8 + ncol);

    __syncthreads();    // all LDSM reads of xs done before staging overwrites it

    #pragma unroll
    for (int mt = 0; mt < 2; mt++) {
        const int r_lo = m_warp + mt * 16 + mrow;
        const int r_hi = r_lo + 8;
        const float xn_lo = xn[r_lo];
        const float xn_hi = xn[r_hi];
        #pragma unroll
        for (int nt = 0; nt < 4; nt++) {
            float2 o0, o1;
            o0.x = c[mt][nt][0] + xn_lo + ynr[nt].x;
            o0.y = c[mt][nt][1] + xn_lo + ynr[nt].y;
            o1.x = c[mt][nt][2] + xn_hi + ynr[nt].x;
            o1.y = c[mt][nt][3] + xn_hi + ynr[nt].y;
            const uint32_t off = (uint32_t)(4 * (n_warp + nt * 8 + ncol));
            const uint32_t g   = off >> 4;
            const uint32_t rem = off & 15u;
            uint32_t a0 = sbase + SM_XS + (uint32_t)r_lo * 256u
                        + ((g ^ (((uint32_t)r_lo & 7u) << 1)) << 4) + rem;
            uint32_t a1 = sbase + SM_XS + (uint32_t)r_hi * 256u
                        + ((g ^ (((uint32_t)r_hi & 7u) << 1)) << 4) + rem;
            asm volatile("st.shared.v2.f32 [%0], {%1, %2};"
                         :: "r"(a0), "f"(o0.x), "f"(o0.y) : "memory");
            asm volatile("st.shared.v2.f32 [%0], {%1, %2};"
                         :: "r"(a1), "f"(o1.x), "f"(o1.y) : "memory");
        }
    }
    __syncthreads();

    // cooperative copy-out: 2048 16B granules, warp covers 2 rows contiguously
    #pragma unroll
    for (int it = 0; it < 8; it++) {
        const uint32_t gid = (uint32_t)(it * 256 + tid);
        const uint32_t r = gid >> 4;
        const uint32_t g = gid & 15u;
        uint32_t v0, v1, v2, v3;
        uint32_t src = sbase + SM_XS + r * 256u + ((g ^ ((r & 7u) << 1)) << 4);
        asm volatile("ld.shared.v4.u32 {%0,%1,%2,%3}, [%4];"
                     : "=r"(v0), "=r"(v1), "=r"(v2), "=r"(v3) : "r"(src));
        uint4 w = make_uint4(v0, v1, v2, v3);
        *(uint4*)(ob + (size_t)(i0 + r) * n + j0 + g * 4) = w;
    }
}

extern "C" void kernel_launch(void* const* d_in, const int* in_sizes, int n_in,
                              void* d_out, int out_size) {
    const float* x = (const float*)d_in[0];
    const float* y = (const float*)d_in[1];
    float* out = (float*)d_out;

    const int B = 2;
    int n = in_sizes[0] / (B * Dk);       // 2048
    if (n <= 0) n = 2048;

    // prep: one thread per quarter-row of x and y
    int total_threads = 2 * B * n * 4;
    prep_kernel<<<(total_threads + 255) / 256, 256>>>(x, y, n);

    cudaFuncSetAttribute(PairwiseDistance_tf32_kernel,
                         cudaFuncAttributeMaxDynamicSharedMemorySize, SM_TOTAL);
    dim3 grid(n / 64, n / 128, B);
    PairwiseDistance_tf32_kernel<<<grid, NTHREADS, SM_TOTAL>>>(out, n);
}